// round 3
// baseline (speedup 1.0000x reference)
#include <cuda_runtime.h>
#include <math.h>

#define DD 128
#define NPAD 100096

// Scratch (device globals: no allocation allowed)
static __device__ float g_hW  [(size_t)NPAD * DD];   // 51.2 MB
static __device__ float g_agg [(size_t)NPAD * DD];   // 51.2 MB
static __device__ float g_G1  [(size_t)NPAD * 384];  // 153.7 MB  (gx)
static __device__ float g_G2  [(size_t)NPAD * 384];  // 153.7 MB  (gh)
static __device__ float g_WihT[256 * 384];
static __device__ float g_WhhT[128 * 384];

// Packed f32x2 FMA: c(pair) += a(pair) * b(pair)
#define FMA2(c, a, b) \
    asm("fma.rn.f32x2 %0, %1, %2, %0;" : "+l"(c) : "l"(a), "l"(b))
// Duplicate one f32 into both halves of a 64-bit pair
#define DUP2(d, s) \
    asm("mov.b64 %0, {%1, %1};" : "=l"(d) : "f"(s))

// ---------------------------------------------------------------------------
// Weight transpose: WihT[k][j] = w_ih[j][k] (j<384,k<256); WhhT likewise.
// ---------------------------------------------------------------------------
__global__ __launch_bounds__(256) void prep_weights(const float* __restrict__ w_ih,
                                                    const float* __restrict__ w_hh) {
    int tid = blockIdx.x * 256 + threadIdx.x;
    if (tid < 256 * 384) {
        int k = tid / 384, j = tid - k * 384;
        g_WihT[tid] = w_ih[j * 256 + k];
    } else {
        int t2 = tid - 256 * 384;
        if (t2 < 128 * 384) {
            int k = t2 / 384, j = t2 - k * 384;
            g_WhhT[t2] = w_hh[j * 128 + k];
        }
    }
}

// ---------------------------------------------------------------------------
// Packed 8x8 microtile compute from smem tiles (16 k-steps).
// acc2[i][j2] holds the pair (acc[i][2*j2], acc[i][2*j2+1]).
// ---------------------------------------------------------------------------
__device__ __forceinline__ void compute_tile(const float (*As)[132], const float (*Bs)[132],
                                             int ty, int tx,
                                             unsigned long long acc2[8][4]) {
#pragma unroll
    for (int k = 0; k < 16; k++) {
        float4 af0 = *(const float4*)&As[k][ty * 8];
        float4 af1 = *(const float4*)&As[k][ty * 8 + 4];
        unsigned long long ad[8];
        DUP2(ad[0], af0.x); DUP2(ad[1], af0.y); DUP2(ad[2], af0.z); DUP2(ad[3], af0.w);
        DUP2(ad[4], af1.x); DUP2(ad[5], af1.y); DUP2(ad[6], af1.z); DUP2(ad[7], af1.w);
        unsigned long long b2[4];
        b2[0] = *(const unsigned long long*)&Bs[k][tx * 8];
        b2[1] = *(const unsigned long long*)&Bs[k][tx * 8 + 2];
        b2[2] = *(const unsigned long long*)&Bs[k][tx * 8 + 4];
        b2[3] = *(const unsigned long long*)&Bs[k][tx * 8 + 6];
#pragma unroll
        for (int i = 0; i < 8; i++)
#pragma unroll
            for (int j = 0; j < 4; j++) FMA2(acc2[i][j], ad[i], b2[j]);
    }
}

// ---------------------------------------------------------------------------
// GEMM A: hW[m][:] = ent[nid[m]][:] @ W   (M x 128 x 128)
// 128x128 tile, BK=16, 256 threads, 8x8 microtile, f32x2-packed, SW pipelined.
// ---------------------------------------------------------------------------
__global__ __launch_bounds__(256) void gemmA(const float* __restrict__ ent,
                                             const int*   __restrict__ nid,
                                             const float* __restrict__ W, int M) {
    __shared__ float As[16][132];
    __shared__ float Bs[16][132];
    const int tid  = threadIdx.x;
    const int m0   = blockIdx.x * 128;
    const int arow = tid >> 1;
    const int kseg = (tid & 1) * 8;
    const int m    = m0 + arow;
    const float* arowp = (m < M) ? ent + (size_t)nid[m] * DD : (const float*)0;
    const int r0 = (tid * 2) >> 5,       c0b = ((tid * 2) & 31) * 4;
    const int r1 = (tid * 2 + 1) >> 5,   c1b = ((tid * 2 + 1) & 31) * 4;
    const int ty = tid >> 4, tx = tid & 15;

    unsigned long long acc2[8][4];
#pragma unroll
    for (int i = 0; i < 8; i++)
#pragma unroll
        for (int j = 0; j < 4; j++) acc2[i][j] = 0ULL;

    float av[8]; float4 bv0, bv1;
    // prefetch kt=0
    if (arowp) {
        float4 a0 = *(const float4*)(arowp + kseg);
        float4 a1 = *(const float4*)(arowp + kseg + 4);
        av[0]=a0.x; av[1]=a0.y; av[2]=a0.z; av[3]=a0.w;
        av[4]=a1.x; av[5]=a1.y; av[6]=a1.z; av[7]=a1.w;
    } else {
#pragma unroll
        for (int i = 0; i < 8; i++) av[i] = 0.f;
    }
    bv0 = *(const float4*)(W + r0 * DD + c0b);
    bv1 = *(const float4*)(W + r1 * DD + c1b);

    for (int kt = 0; kt < 8; kt++) {
#pragma unroll
        for (int i = 0; i < 8; i++) As[kseg + i][arow] = av[i];
        *(float4*)&Bs[r0][c0b] = bv0;
        *(float4*)&Bs[r1][c1b] = bv1;
        __syncthreads();
        if (kt + 1 < 8) {
            int koff = (kt + 1) * 16;
            if (arowp) {
                float4 a0 = *(const float4*)(arowp + koff + kseg);
                float4 a1 = *(const float4*)(arowp + koff + kseg + 4);
                av[0]=a0.x; av[1]=a0.y; av[2]=a0.z; av[3]=a0.w;
                av[4]=a1.x; av[5]=a1.y; av[6]=a1.z; av[7]=a1.w;
            }
            bv0 = *(const float4*)(W + (koff + r0) * DD + c0b);
            bv1 = *(const float4*)(W + (koff + r1) * DD + c1b);
        }
        compute_tile(As, Bs, ty, tx, acc2);
        __syncthreads();
    }
#pragma unroll
    for (int i = 0; i < 8; i++) {
        int mm = m0 + ty * 8 + i;
        if (mm < M) {
            *(ulonglong2*)&g_hW[(size_t)mm * DD + tx * 8]     = make_ulonglong2(acc2[i][0], acc2[i][1]);
            *(ulonglong2*)&g_hW[(size_t)mm * DD + tx * 8 + 4] = make_ulonglong2(acc2[i][2], acc2[i][3]);
        }
    }
}

// ---------------------------------------------------------------------------
// Edge scatter: one warp per edge; agg[dst] += hW[src], 128 floats per edge,
// vectorized f32x4 reduction (sm_90+).
// ---------------------------------------------------------------------------
__global__ __launch_bounds__(256) void scatter_edges(const int* __restrict__ src,
                                                     const int* __restrict__ dst, int E) {
    int gw   = (blockIdx.x * 256 + threadIdx.x) >> 5;
    int lane = threadIdx.x & 31;
    if (gw >= E) return;
    int s = __ldg(&src[gw]);
    int d = __ldg(&dst[gw]);
    float4 v = *((const float4*)(g_hW + (size_t)s * DD) + lane);
    float* addr = g_agg + (size_t)d * DD + lane * 4;
    asm volatile("red.global.add.v4.f32 [%0], {%1,%2,%3,%4};"
                 :: "l"(addr), "f"(v.x), "f"(v.y), "f"(v.z), "f"(v.w) : "memory");
}

// ---------------------------------------------------------------------------
// GEMM G: C[m][c0:c0+128] = sum_k A(m,k) * Bt[k][c]
// Two K-phases: phase0 = A0 row * rowscale (nkt0*16 k's), phase1 = A1 row.
// Bt is [K_total][384]. f32x2-packed, SW pipelined.
// ---------------------------------------------------------------------------
__global__ __launch_bounds__(256) void gemmG(const float* __restrict__ A0,
                                             const float* __restrict__ rs,
                                             const float* __restrict__ A1,
                                             const float* __restrict__ Bt,
                                             float* __restrict__ C,
                                             int M, int nkt0, int nkt1) {
    __shared__ float As[16][132];
    __shared__ float Bs[16][132];
    const int tid  = threadIdx.x;
    const int m0   = blockIdx.x * 128;
    const int c0   = blockIdx.y * 128;
    const int arow = tid >> 1;
    const int kseg = (tid & 1) * 8;
    const int m    = m0 + arow;
    const bool mval = (m < M);
    const float scale = (mval && rs) ? rs[m] : 1.f;
    const float* a0p = mval ? A0 + (size_t)m * DD : (const float*)0;
    const float* a1p = (mval && A1) ? A1 + (size_t)m * DD : (const float*)0;
    const int r0 = (tid * 2) >> 5,       c0b = ((tid * 2) & 31) * 4;
    const int r1 = (tid * 2 + 1) >> 5,   c1b = ((tid * 2 + 1) & 31) * 4;
    const int ty = tid >> 4, tx = tid & 15;
    const int nkt = nkt0 + nkt1;

    unsigned long long acc2[8][4];
#pragma unroll
    for (int i = 0; i < 8; i++)
#pragma unroll
        for (int j = 0; j < 4; j++) acc2[i][j] = 0ULL;

    float av[8]; float4 bv0, bv1;

    auto loadA = [&](int kt, float avv[8]) {
        const float* ap; float sc; int koff;
        if (kt < nkt0) { ap = a0p; sc = scale; koff = kt * 16; }
        else           { ap = a1p; sc = 1.f;   koff = (kt - nkt0) * 16; }
        if (ap) {
            float4 a0v = *(const float4*)(ap + koff + kseg);
            float4 a1v = *(const float4*)(ap + koff + kseg + 4);
            avv[0]=a0v.x*sc; avv[1]=a0v.y*sc; avv[2]=a0v.z*sc; avv[3]=a0v.w*sc;
            avv[4]=a1v.x*sc; avv[5]=a1v.y*sc; avv[6]=a1v.z*sc; avv[7]=a1v.w*sc;
        } else {
#pragma unroll
            for (int i = 0; i < 8; i++) avv[i] = 0.f;
        }
    };
    auto loadB = [&](int kt, float4& b0v, float4& b1v) {
        b0v = *(const float4*)(Bt + (size_t)(kt * 16 + r0) * 384 + c0 + c0b);
        b1v = *(const float4*)(Bt + (size_t)(kt * 16 + r1) * 384 + c0 + c1b);
    };

    loadA(0, av); loadB(0, bv0, bv1);
    for (int kt = 0; kt < nkt; kt++) {
#pragma unroll
        for (int i = 0; i < 8; i++) As[kseg + i][arow] = av[i];
        *(float4*)&Bs[r0][c0b] = bv0;
        *(float4*)&Bs[r1][c1b] = bv1;
        __syncthreads();
        if (kt + 1 < nkt) { loadA(kt + 1, av); loadB(kt + 1, bv0, bv1); }
        compute_tile(As, Bs, ty, tx, acc2);
        __syncthreads();
    }
#pragma unroll
    for (int i = 0; i < 8; i++) {
        int mm = m0 + ty * 8 + i;
        if (mm < M) {
            *(ulonglong2*)&C[(size_t)mm * 384 + c0 + tx * 8]     = make_ulonglong2(acc2[i][0], acc2[i][1]);
            *(ulonglong2*)&C[(size_t)mm * 384 + c0 + tx * 8 + 4] = make_ulonglong2(acc2[i][2], acc2[i][3]);
        }
    }
}

// ---------------------------------------------------------------------------
// GRU gates + ReLU + L2 normalize. One warp per node, 4 dims per lane.
// ---------------------------------------------------------------------------
__device__ __forceinline__ float sigmoidf_(float x) { return 1.f / (1.f + __expf(-x)); }

__global__ __launch_bounds__(256) void gru_norm(const float* __restrict__ hbias,
                                                const float* __restrict__ b_ih,
                                                const float* __restrict__ b_hh,
                                                float* __restrict__ out, int M) {
    int w    = (blockIdx.x * 256 + threadIdx.x) >> 5;
    int lane = threadIdx.x & 31;
    if (w >= M) return;
    const float* g1 = g_G1 + (size_t)w * 384;
    const float* g2 = g_G2 + (size_t)w * 384;
    int j = lane * 4;
    float4 xr  = *(const float4*)(g1 + j);
    float4 xz  = *(const float4*)(g1 + 128 + j);
    float4 xn  = *(const float4*)(g1 + 256 + j);
    float4 hr  = *(const float4*)(g2 + j);
    float4 hz  = *(const float4*)(g2 + 128 + j);
    float4 hn  = *(const float4*)(g2 + 256 + j);
    float4 hh  = *(const float4*)(hbias + (size_t)w * DD + j);
    float4 bir = *(const float4*)(b_ih + j);
    float4 biz = *(const float4*)(b_ih + 128 + j);
    float4 bin_= *(const float4*)(b_ih + 256 + j);
    float4 bhr = *(const float4*)(b_hh + j);
    float4 bhz = *(const float4*)(b_hh + 128 + j);
    float4 bhn = *(const float4*)(b_hh + 256 + j);

    float ss = 0.f; float4 res;
#define GRU1(c) { \
    float rg = sigmoidf_(xr.c + bir.c + hr.c + bhr.c); \
    float zg = sigmoidf_(xz.c + biz.c + hz.c + bhz.c); \
    float ng = tanhf(xn.c + bin_.c + rg * (hn.c + bhn.c)); \
    float hv = (1.f - zg) * ng + zg * hh.c; \
    hv = fmaxf(hv, 0.f); \
    res.c = hv; ss += hv * hv; }
    GRU1(x) GRU1(y) GRU1(z) GRU1(w)
#undef GRU1
#pragma unroll
    for (int off = 16; off; off >>= 1) ss += __shfl_xor_sync(0xffffffffu, ss, off);
    float inv = 1.f / fmaxf(sqrtf(ss), 1e-12f);
    res.x *= inv; res.y *= inv; res.z *= inv; res.w *= inv;
    *(float4*)(out + (size_t)w * DD + j) = res;
}

// ---------------------------------------------------------------------------
extern "C" void kernel_launch(void* const* d_in, const int* in_sizes, int n_in,
                              void* d_out, int out_size) {
    const float* ent   = (const float*)d_in[0];
    // d_in[1] = rel_embs (unused by reference)
    const float* e_r   = (const float*)d_in[2];
    const float* onorm = (const float*)d_in[3];
    const float* W     = (const float*)d_in[4];
    const float* w_ih  = (const float*)d_in[5];
    const float* w_hh  = (const float*)d_in[6];
    const float* b_ih  = (const float*)d_in[7];
    const float* b_hh  = (const float*)d_in[8];
    const int*   nid   = (const int*)d_in[9];
    const int*   esrc  = (const int*)d_in[10];
    const int*   edst  = (const int*)d_in[11];
    const int M = in_sizes[2] / DD;
    const int E = in_sizes[10];
    float* out = (float*)d_out;

    void* pv;
    cudaGetSymbolAddress(&pv, g_agg);   float* aggp  = (float*)pv;
    cudaGetSymbolAddress(&pv, g_WihT);  float* wihtp = (float*)pv;
    cudaGetSymbolAddress(&pv, g_WhhT);  float* whhtp = (float*)pv;
    cudaGetSymbolAddress(&pv, g_G1);    float* g1p   = (float*)pv;
    cudaGetSymbolAddress(&pv, g_G2);    float* g2p   = (float*)pv;

    cudaMemsetAsync(aggp, 0, (size_t)M * DD * sizeof(float), 0);
    prep_weights<<<576, 256>>>(w_ih, w_hh);
    gemmA<<<(M + 127) / 128, 256>>>(ent, nid, W, M);
    scatter_edges<<<(E + 7) / 8, 256>>>(esrc, edst, E);
    dim3 gg((M + 127) / 128, 3);
    // gx = [agg*out_norm, e_r_bias] @ WihT
    gemmG<<<gg, 256>>>(aggp, onorm, e_r, wihtp, g1p, M, 8, 8);
    // gh = e_r_bias @ WhhT
    gemmG<<<gg, 256>>>(e_r, (const float*)0, (const float*)0, whhtp, g2p, M, 8, 0);
    gru_norm<<<(M + 7) / 8, 256>>>(e_r, b_ih, b_hh, out, M);
}

// round 17
// speedup vs baseline: 1.5719x; 1.5719x over previous
#include <cuda_runtime.h>
#include <cuda_bf16.h>
#include <cstdint>
#include <math.h>

#define DD 128
#define NPAD 100096

// ------------------------- device scratch (no allocs) -----------------------
static __device__ float g_hW  [(size_t)NPAD * DD];    // gemmA out (fp32)
static __device__ float g_agg [(size_t)NPAD * DD];    // scatter accum
static __device__ float g_G1  [(size_t)NPAD * 384];   // gx
static __device__ float g_G2  [(size_t)NPAD * 384];   // gh
static __device__ __nv_bfloat16 g_Ae [(size_t)NPAD * 256];  // [ent_hi|ent_lo]
static __device__ __nv_bfloat16 g_Ax [(size_t)NPAD * 512];  // [aggn_hi|er_hi|aggn_lo|er_lo]
static __device__ __nv_bfloat16 g_Bgx[384 * 768];     // [wih_hi|wih_hi|wih_lo]
static __device__ __nv_bfloat16 g_Bgh[384 * 384];     // [whh_hi|whh_hi|whh_lo]
static __device__ __nv_bfloat16 g_BW [128 * 384];     // [Wt_hi|Wt_hi|Wt_lo]

__device__ __forceinline__ uint32_t smem_u32(const void* p) {
    uint32_t a;
    asm("{ .reg .u64 t; cvta.to.shared.u64 t, %1; cvt.u32.u64 %0, t; }" : "=r"(a) : "l"(p));
    return a;
}

// ------------------------- prep kernels -------------------------------------
__device__ __forceinline__ void bsplit(float x, __nv_bfloat16& h, __nv_bfloat16& l) {
    h = __float2bfloat16(x);
    l = __float2bfloat16(x - __bfloat162float(h));
}

__global__ __launch_bounds__(256) void prep_B(const float* __restrict__ w_ih,
                                              const float* __restrict__ w_hh,
                                              const float* __restrict__ W) {
    int t = blockIdx.x * 256 + threadIdx.x;
    if (t < 384 * 768) {
        int n = t / 768, k = t - n * 768;
        int reg = k >> 8, kk = k & 255;
        float x = w_ih[n * 256 + kk];
        __nv_bfloat16 h, l; bsplit(x, h, l);
        g_Bgx[t] = (reg < 2) ? h : l;
    } else if (t < 384 * 768 + 384 * 384) {
        int t2 = t - 384 * 768;
        int n = t2 / 384, k = t2 - n * 384;
        int reg = k >> 7, kk = k & 127;
        float x = w_hh[n * 128 + kk];
        __nv_bfloat16 h, l; bsplit(x, h, l);
        g_Bgh[t2] = (reg < 2) ? h : l;
    } else if (t < 384 * 768 + 384 * 384 + 128 * 384) {
        int t3 = t - 384 * 768 - 384 * 384;
        int n = t3 / 384, k = t3 - n * 384;
        int reg = k >> 7, kk = k & 127;
        float x = W[kk * 128 + n];   // W^T[n][kk]
        __nv_bfloat16 h, l; bsplit(x, h, l);
        g_BW[t3] = (reg < 2) ? h : l;
    }
}

__global__ __launch_bounds__(256) void prep_Ae(const float* __restrict__ ent,
                                               const int* __restrict__ nid, int M) {
    int idx = blockIdx.x * 256 + threadIdx.x;
    if (idx >= M * 128) return;
    int m = idx >> 7, k = idx & 127;
    float x = ent[(size_t)nid[m] * 128 + k];
    __nv_bfloat16 h, l; bsplit(x, h, l);
    g_Ae[(size_t)m * 256 + k]       = h;
    g_Ae[(size_t)m * 256 + 128 + k] = l;
}

__global__ __launch_bounds__(256) void prep_Agx(const float* __restrict__ onorm,
                                                const float* __restrict__ e_r, int M) {
    int idx = blockIdx.x * 256 + threadIdx.x;
    if (idx >= M * 128) return;
    int m = idx >> 7, k = idx & 127;
    float a = g_agg[(size_t)m * 128 + k] * onorm[m];
    float e = e_r[(size_t)m * 128 + k];
    __nv_bfloat16 ah, al, eh, el;
    bsplit(a, ah, al); bsplit(e, eh, el);
    size_t b = (size_t)m * 512;
    g_Ax[b + k]       = ah;
    g_Ax[b + 128 + k] = eh;
    g_Ax[b + 256 + k] = al;
    g_Ax[b + 384 + k] = el;
}

// ------------------------- HMMA GEMM (mma.sync, sm_80+ path) ----------------
// C[m0:m0+128, n0:n0+128] = sum over nch K-chunks (32 wide) of A-slices @ B^T.
// A: bf16 rows [M, lda], per-chunk column offset co.a[c]. B: bf16 rows [N, ldb]
// (K-major), chunk c reads B cols [c*32, c*32+32).
struct ChunkOffs { int a[24]; };

#define SROW 80   // smem row stride bytes (conflict-free for ldmatrix)

__global__ __launch_bounds__(256) void mgemm(const __nv_bfloat16* __restrict__ A, int lda,
                                             const __nv_bfloat16* __restrict__ B, int ldb,
                                             float* __restrict__ C, int ldc,
                                             int M, int nch, ChunkOffs co) {
    __shared__ __align__(16) uint8_t smA[2][128 * SROW];
    __shared__ __align__(16) uint8_t smB[2][128 * SROW];

    const int tid  = threadIdx.x;
    const int wid  = tid >> 5, lane = tid & 31;
    const int m0   = blockIdx.x * 128;
    const int n0   = blockIdx.y * 128;
    const int warp_m = (wid & 3) * 32;
    const int warp_n = (wid >> 2) * 64;

    float acc[2][8][4];
#pragma unroll
    for (int i = 0; i < 2; i++)
#pragma unroll
        for (int j = 0; j < 8; j++)
#pragma unroll
            for (int q = 0; q < 4; q++) acc[i][j][q] = 0.f;

    // ---- async stage loader: 128 rows x 32 bf16 (64B) each for A and B ----
    auto issue_load = [&](int c, int buf) {
        int aoff = co.a[c], boff = c * 32;
#pragma unroll
        for (int i = 0; i < 2; i++) {
            int idx = tid + i * 256;           // 0..511
            int row = idx >> 2, kc = idx & 3;  // row 0..127, 16B chunk 0..3
            uint32_t da = smem_u32(&smA[buf][row * SROW + kc * 16]);
            const __nv_bfloat16* ga = A + (size_t)(m0 + row) * lda + aoff + kc * 8;
            int sz = (m0 + row < M) ? 16 : 0;
            asm volatile("cp.async.ca.shared.global [%0], [%1], 16, %2;"
                         :: "r"(da), "l"(ga), "r"(sz));
            uint32_t db = smem_u32(&smB[buf][row * SROW + kc * 16]);
            const __nv_bfloat16* gb = B + (size_t)(n0 + row) * ldb + boff + kc * 8;
            asm volatile("cp.async.ca.shared.global [%0], [%1], 16;"
                         :: "r"(db), "l"(gb));
        }
        asm volatile("cp.async.commit_group;" ::: "memory");
    };

    issue_load(0, 0);

    const int mat = lane >> 3, mrow = lane & 7;

    for (int c = 0; c < nch; c++) {
        if (c + 1 < nch) {
            issue_load(c + 1, (c + 1) & 1);
            asm volatile("cp.async.wait_group 1;" ::: "memory");
        } else {
            asm volatile("cp.async.wait_group 0;" ::: "memory");
        }
        __syncthreads();

        const int buf = c & 1;
        const uint32_t baseA = smem_u32(&smA[buf][0]);
        const uint32_t baseB = smem_u32(&smB[buf][0]);

#pragma unroll
        for (int s = 0; s < 2; s++) {          // two k16 steps per 32-chunk
            const int k0 = s * 16;
            uint32_t af[2][4];
#pragma unroll
            for (int mb = 0; mb < 2; mb++) {
                int m = warp_m + mb * 16 + (mat & 1) * 8 + mrow;
                int k = k0 + (mat >> 1) * 8;
                uint32_t ad = baseA + m * SROW + k * 2;
                asm volatile("ldmatrix.sync.aligned.m8n8.x4.shared.b16 {%0,%1,%2,%3}, [%4];"
                             : "=r"(af[mb][0]), "=r"(af[mb][1]),
                               "=r"(af[mb][2]), "=r"(af[mb][3]) : "r"(ad));
            }
            uint32_t bf[8][2];
#pragma unroll
            for (int g = 0; g < 4; g++) {
                int n = warp_n + g * 16 + (mat >> 1) * 8 + mrow;
                int k = k0 + (mat & 1) * 8;
                uint32_t bd = baseB + n * SROW + k * 2;
                uint32_t q0, q1, q2, q3;
                asm volatile("ldmatrix.sync.aligned.m8n8.x4.shared.b16 {%0,%1,%2,%3}, [%4];"
                             : "=r"(q0), "=r"(q1), "=r"(q2), "=r"(q3) : "r"(bd));
                bf[2 * g][0] = q0;     bf[2 * g][1] = q1;
                bf[2 * g + 1][0] = q2; bf[2 * g + 1][1] = q3;
            }
#pragma unroll
            for (int mb = 0; mb < 2; mb++)
#pragma unroll
                for (int nb = 0; nb < 8; nb++)
                    asm volatile(
                        "mma.sync.aligned.m16n8k16.row.col.f32.bf16.bf16.f32 "
                        "{%0,%1,%2,%3}, {%4,%5,%6,%7}, {%8,%9}, {%0,%1,%2,%3};"
                        : "+f"(acc[mb][nb][0]), "+f"(acc[mb][nb][1]),
                          "+f"(acc[mb][nb][2]), "+f"(acc[mb][nb][3])
                        : "r"(af[mb][0]), "r"(af[mb][1]), "r"(af[mb][2]), "r"(af[mb][3]),
                          "r"(bf[nb][0]), "r"(bf[nb][1]));
        }
        __syncthreads();
    }

    // ---- epilogue: fragment -> global fp32 ----
#pragma unroll
    for (int mb = 0; mb < 2; mb++) {
        int r0 = m0 + warp_m + mb * 16 + (lane >> 2);
#pragma unroll
        for (int nb = 0; nb < 8; nb++) {
            int col = n0 + warp_n + nb * 8 + (lane & 3) * 2;
            if (r0 < M)
                *(float2*)&C[(size_t)r0 * ldc + col] = make_float2(acc[mb][nb][0], acc[mb][nb][1]);
            if (r0 + 8 < M)
                *(float2*)&C[(size_t)(r0 + 8) * ldc + col] = make_float2(acc[mb][nb][2], acc[mb][nb][3]);
        }
    }
}

// ------------------------- edge scatter -------------------------------------
__global__ __launch_bounds__(256) void scatter_edges(const int* __restrict__ src,
                                                     const int* __restrict__ dst, int E) {
    int gw   = (blockIdx.x * 256 + threadIdx.x) >> 5;
    int lane = threadIdx.x & 31;
    if (gw >= E) return;
    int s = __ldg(&src[gw]);
    int d = __ldg(&dst[gw]);
    float4 v = *((const float4*)(g_hW + (size_t)s * DD) + lane);
    float* addr = g_agg + (size_t)d * DD + lane * 4;
    asm volatile("red.global.add.v4.f32 [%0], {%1,%2,%3,%4};"
                 :: "l"(addr), "f"(v.x), "f"(v.y), "f"(v.z), "f"(v.w) : "memory");
}

// ------------------------- GRU + ReLU + L2 norm ------------------------------
__device__ __forceinline__ float sigmoidf_(float x) { return 1.f / (1.f + __expf(-x)); }

__global__ __launch_bounds__(256) void gru_norm(const float* __restrict__ hbias,
                                                const float* __restrict__ b_ih,
                                                const float* __restrict__ b_hh,
                                                float* __restrict__ out, int M) {
    int w    = (blockIdx.x * 256 + threadIdx.x) >> 5;
    int lane = threadIdx.x & 31;
    if (w >= M) return;
    const float* g1 = g_G1 + (size_t)w * 384;
    const float* g2 = g_G2 + (size_t)w * 384;
    int j = lane * 4;
    float4 xr  = *(const float4*)(g1 + j);
    float4 xz  = *(const float4*)(g1 + 128 + j);
    float4 xn  = *(const float4*)(g1 + 256 + j);
    float4 hr  = *(const float4*)(g2 + j);
    float4 hz  = *(const float4*)(g2 + 128 + j);
    float4 hn  = *(const float4*)(g2 + 256 + j);
    float4 hh  = *(const float4*)(hbias + (size_t)w * DD + j);
    float4 bir = *(const float4*)(b_ih + j);
    float4 biz = *(const float4*)(b_ih + 128 + j);
    float4 bin_= *(const float4*)(b_ih + 256 + j);
    float4 bhr = *(const float4*)(b_hh + j);
    float4 bhz = *(const float4*)(b_hh + 128 + j);
    float4 bhn = *(const float4*)(b_hh + 256 + j);

    float ss = 0.f; float4 res;
#define GRU1(c) { \
    float rg = sigmoidf_(xr.c + bir.c + hr.c + bhr.c); \
    float zg = sigmoidf_(xz.c + biz.c + hz.c + bhz.c); \
    float ng = tanhf(xn.c + bin_.c + rg * (hn.c + bhn.c)); \
    float hv = (1.f - zg) * ng + zg * hh.c; \
    hv = fmaxf(hv, 0.f); \
    res.c = hv; ss += hv * hv; }
    GRU1(x) GRU1(y) GRU1(z) GRU1(w)
#undef GRU1
#pragma unroll
    for (int off = 16; off; off >>= 1) ss += __shfl_xor_sync(0xffffffffu, ss, off);
    float inv = 1.f / fmaxf(sqrtf(ss), 1e-12f);
    res.x *= inv; res.y *= inv; res.z *= inv; res.w *= inv;
    *(float4*)(out + (size_t)w * DD + j) = res;
}

// ---------------------------------------------------------------------------
extern "C" void kernel_launch(void* const* d_in, const int* in_sizes, int n_in,
                              void* d_out, int out_size) {
    const float* ent   = (const float*)d_in[0];
    const float* e_r   = (const float*)d_in[2];
    const float* onorm = (const float*)d_in[3];
    const float* W     = (const float*)d_in[4];
    const float* w_ih  = (const float*)d_in[5];
    const float* w_hh  = (const float*)d_in[6];
    const float* b_ih  = (const float*)d_in[7];
    const float* b_hh  = (const float*)d_in[8];
    const int*   nid   = (const int*)d_in[9];
    const int*   esrc  = (const int*)d_in[10];
    const int*   edst  = (const int*)d_in[11];
    const int M = in_sizes[2] / DD;
    const int E = in_sizes[10];
    float* out = (float*)d_out;

    void* pv;
    cudaGetSymbolAddress(&pv, g_agg);  float* aggp = (float*)pv;
    cudaGetSymbolAddress(&pv, g_hW);   float* hwp  = (float*)pv;
    cudaGetSymbolAddress(&pv, g_G1);   float* g1p  = (float*)pv;
    cudaGetSymbolAddress(&pv, g_G2);   float* g2p  = (float*)pv;
    cudaGetSymbolAddress(&pv, g_Ae);   __nv_bfloat16* aep = (__nv_bfloat16*)pv;
    cudaGetSymbolAddress(&pv, g_Ax);   __nv_bfloat16* axp = (__nv_bfloat16*)pv;
    cudaGetSymbolAddress(&pv, g_Bgx);  __nv_bfloat16* bgx = (__nv_bfloat16*)pv;
    cudaGetSymbolAddress(&pv, g_Bgh);  __nv_bfloat16* bgh = (__nv_bfloat16*)pv;
    cudaGetSymbolAddress(&pv, g_BW);   __nv_bfloat16* bw  = (__nv_bfloat16*)pv;

    const int mtiles = (M + 127) / 128;

    cudaMemsetAsync(aggp, 0, (size_t)M * DD * sizeof(float), 0);
    prep_B<<<(491520 + 255) / 256, 256>>>(w_ih, w_hh, W);
    prep_Ae<<<(M * 128 + 255) / 256, 256>>>(ent, nid, M);

    // hW = ent[nid] @ W : A=[hi|lo] (lda 256), B=[Wt_hi|Wt_hi|Wt_lo] (ldb 384)
    ChunkOffs cA;
    {
        int s[12] = {0,32,64,96, 128,160,192,224, 0,32,64,96};
        for (int i = 0; i < 24; i++) cA.a[i] = (i < 12) ? s[i] : 0;
    }
    mgemm<<<dim3(mtiles, 1), 256>>>(aep, 256, bw, 384, hwp, 128, M, 12, cA);

    scatter_edges<<<(E + 7) / 8, 256>>>(esrc, edst, E);
    prep_Agx<<<(M * 128 + 255) / 256, 256>>>(onorm, e_r, M);

    // gx: A=[aggn_hi|er_hi|aggn_lo|er_lo] (512), B=[wih_hi|wih_hi|wih_lo] (768)
    ChunkOffs cX;
    for (int i = 0; i < 8;  i++) cX.a[i]      = i * 32;        // hi·hi
    for (int i = 0; i < 8;  i++) cX.a[8 + i]  = 256 + i * 32;  // lo·hi
    for (int i = 0; i < 8;  i++) cX.a[16 + i] = i * 32;        // hi·lo
    mgemm<<<dim3(mtiles, 3), 256>>>(axp, 512, bgx, 768, g1p, 384, M, 24, cX);

    // gh: A er_hi @128, er_lo @384; B=[whh_hi|whh_hi|whh_lo] (384)
    ChunkOffs cH;
    {
        int s[12] = {128,160,192,224, 384,416,448,480, 128,160,192,224};
        for (int i = 0; i < 24; i++) cH.a[i] = (i < 12) ? s[i] : 0;
    }
    mgemm<<<dim3(mtiles, 3), 256>>>(axp, 512, bgh, 384, g2p, 384, M, 12, cH);

    gru_norm<<<(M + 7) / 8, 256>>>(e_r, b_ih, b_hh, out, M);
}